// round 9
// baseline (speedup 1.0000x reference)
#include <cuda_runtime.h>
#include <cuda_fp16.h>
#include <cstdint>

// Problem dims (fixed by the dataset)
constexpr int B  = 8;
constexpr int TQ = 2048;
constexpr int TK = 2048;
constexpr int D  = 1024;
constexpr float NEG_INF = -1e9f;

constexpr int KC = 64;                    // K floats per chunk
constexpr int QK_CHUNKS = D  / KC;        // 16
constexpr int PV_CHUNKS = TK / KC;        // 32

// smem pitches (in halfs)
constexpr int PA = 72;                    // 64 used + 8 pad -> 144B rows
constexpr int PB = 136;                   // V tile: 128 used + 8 pad -> 272B rows

constexpr int QK_TILE  = 128 * PA * 2;            // 18432 B
constexpr int QK_STAGE = 4 * QK_TILE;             // Ah, Al, Bh, Bl = 73728
constexpr int QK_MASKO = 3 * QK_STAGE;            // 221184
constexpr int QK_SMEM  = QK_MASKO + 512;

constexpr int PV_PTILE = 128 * PA * 2;            // 18432
constexpr int PV_VTILE = 64 * PB * 2;             // 17408
constexpr int PV_STAGE = 2 * PV_PTILE + PV_VTILE; // 54272
constexpr int PV_SMEM  = 3 * PV_STAGE;            // 162816

constexpr int NT = 512;                   // 16 warps, 4x4 grid, warp tile 32x32

// ------------------------------------------------ device scratch (sanctioned)
__device__ __align__(16) __half g_dec_h[(size_t)B * TQ * D];
__device__ __align__(16) __half g_dec_l[(size_t)B * TQ * D];
__device__ __align__(16) __half g_enc_h[(size_t)B * TK * D];
__device__ __align__(16) __half g_enc_l[(size_t)B * TK * D];
__device__ __align__(16) __half g_p_h[(size_t)B * TQ * TK];
__device__ __align__(16) __half g_p_l[(size_t)B * TQ * TK];

// ---------------------------------------------------------------- helpers
__device__ __forceinline__ uint32_t smem_u32(const void* p) {
    return (uint32_t)__cvta_generic_to_shared(p);
}
__device__ __forceinline__ void cp_async16(uint32_t dst, const void* src) {
    asm volatile("cp.async.cg.shared.global [%0], [%1], 16;\n" :: "r"(dst), "l"(src));
}
__device__ __forceinline__ void cp_commit() {
    asm volatile("cp.async.commit_group;\n");
}
template <int N> __device__ __forceinline__ void cp_wait() {
    asm volatile("cp.async.wait_group %0;\n" :: "n"(N));
}
__device__ __forceinline__ void ldsm4(uint32_t r[4], uint32_t addr) {
    asm volatile("ldmatrix.sync.aligned.m8n8.x4.shared.b16 {%0,%1,%2,%3}, [%4];"
                 : "=r"(r[0]), "=r"(r[1]), "=r"(r[2]), "=r"(r[3]) : "r"(addr));
}
__device__ __forceinline__ void ldsm4t(uint32_t r[4], uint32_t addr) {
    asm volatile("ldmatrix.sync.aligned.m8n8.x4.trans.shared.b16 {%0,%1,%2,%3}, [%4];"
                 : "=r"(r[0]), "=r"(r[1]), "=r"(r[2]), "=r"(r[3]) : "r"(addr));
}
__device__ __forceinline__ void mma16816(float c[4], const uint32_t a[4],
                                         uint32_t b0, uint32_t b1) {
    asm volatile(
        "mma.sync.aligned.m16n8k16.row.col.f32.f16.f16.f32 "
        "{%0,%1,%2,%3},{%4,%5,%6,%7},{%8,%9},{%0,%1,%2,%3};\n"
        : "+f"(c[0]), "+f"(c[1]), "+f"(c[2]), "+f"(c[3])
        : "r"(a[0]), "r"(a[1]), "r"(a[2]), "r"(a[3]), "r"(b0), "r"(b1));
}
__device__ __forceinline__ void split4(float4 v, uint2& hi, uint2& lo) {
    __half2 h0 = __float22half2_rn(make_float2(v.x, v.y));
    __half2 h1 = __float22half2_rn(make_float2(v.z, v.w));
    float2 f0 = __half22float2(h0), f1 = __half22float2(h1);
    __half2 l0 = __float22half2_rn(make_float2(v.x - f0.x, v.y - f0.y));
    __half2 l1 = __float22half2_rn(make_float2(v.z - f1.x, v.w - f1.y));
    hi = make_uint2(*(uint32_t*)&h0, *(uint32_t*)&h1);
    lo = make_uint2(*(uint32_t*)&l0, *(uint32_t*)&l1);
}

// ------------------------------------------------------------ input pre-split
__global__ __launch_bounds__(256) void split_inputs(
    const float* __restrict__ dec, const float* __restrict__ enc)
{
    size_t i = (size_t)blockIdx.x * 256 + threadIdx.x;   // float4 index
    float4 v = ((const float4*)dec)[i];
    uint2 h, l;
    split4(v, h, l);
    ((uint2*)g_dec_h)[i] = h;
    ((uint2*)g_dec_l)[i] = l;
    v = ((const float4*)enc)[i];
    split4(v, h, l);
    ((uint2*)g_enc_h)[i] = h;
    ((uint2*)g_enc_l)[i] = l;
}

// ------------------------------------------------------------ QK^T + mask (fp16 3-term)
// Block tile 128x128x64. 16 warps 4x4, warp tile 32x32. cp.async 3-stage ring.
__global__ __launch_bounds__(NT, 1) void qk_kernel(
    const int* __restrict__ mask, float* __restrict__ S)
{
    extern __shared__ char smem[];
    const int tid = threadIdx.x, warp = tid >> 5, lane = tid & 31;
    const int g = lane >> 2, tg = lane & 3;
    const int r8 = lane & 7, sub = lane >> 3;
    const int wm = warp >> 2, wn = warp & 3;
    const int bz = blockIdx.z, bm = blockIdx.y, bn = blockIdx.x;

    if (tid < 128) ((int*)(smem + QK_MASKO))[tid] = mask[bz * TK + bn * 128 + tid];

    const __half* srcs[4] = {
        g_dec_h + ((size_t)bz * TQ + bm * 128) * D,
        g_dec_l + ((size_t)bz * TQ + bm * 128) * D,
        g_enc_h + ((size_t)bz * TK + bn * 128) * D,
        g_enc_l + ((size_t)bz * TK + bn * 128) * D };

    const uint32_t sb = smem_u32(smem);

    // issue one chunk's 4 tiles into stage k%3
    auto issue = [&](int k) {
        char* base = smem + (k % 3) * QK_STAGE;
        const int ko = k * KC;
#pragma unroll
        for (int t = 0; t < 4; t++) {
            char* dstT = base + t * QK_TILE;
            const __half* src = srcs[t] + ko;
#pragma unroll
            for (int j = 0; j < 2; j++) {
                int u = tid + NT * j, r = u >> 3, c = u & 7;
                cp_async16(smem_u32(dstT + r * 144 + c * 16), src + (size_t)r * D + c * 8);
            }
        }
    };

    issue(0); cp_commit();
    issue(1); cp_commit();

    float acc[2][4][4];
#pragma unroll
    for (int i = 0; i < 2; i++)
#pragma unroll
        for (int j = 0; j < 4; j++)
#pragma unroll
            for (int t = 0; t < 4; t++) acc[i][j][t] = 0.f;

    const uint32_t aoff = (wm * 32 + r8 + (sub & 1) * 8) * 144 + ((sub >> 1) * 8) * 2;
    const uint32_t boff = (wn * 32 + r8 + (sub >> 1) * 8) * 144 + ((sub & 1) * 8) * 2;

    for (int k = 0; k < QK_CHUNKS; k++) {
        cp_wait<1>();
        __syncthreads();               // chunk k visible to all; stage (k+2)%3 reusable
        if (k + 2 < QK_CHUNKS) issue(k + 2);
        cp_commit();                   // always commit (possibly empty group)

        const uint32_t sAh = sb + (k % 3) * QK_STAGE;
        const uint32_t sAl = sAh + QK_TILE;
        const uint32_t sBh = sAl + QK_TILE;
        const uint32_t sBl = sBh + QK_TILE;

        uint32_t fa[2][2][4], fal[2][2][4], fb[2][2][4], fbl[2][2][4];
        // preload kk=0 into buffer 0
#pragma unroll
        for (int i = 0; i < 2; i++) {
            ldsm4(fa[0][i],  sAh + aoff + i * 16 * 144);
            ldsm4(fal[0][i], sAl + aoff + i * 16 * 144);
        }
#pragma unroll
        for (int jp = 0; jp < 2; jp++) {
            ldsm4(fb[0][jp],  sBh + boff + jp * 16 * 144);
            ldsm4(fbl[0][jp], sBl + boff + jp * 16 * 144);
        }
#pragma unroll
        for (int kk = 0; kk < 4; kk++) {
            const int cur = kk & 1, nxt = cur ^ 1;
            if (kk < 3) {
                const uint32_t ko16 = (kk + 1) * 32;
#pragma unroll
                for (int i = 0; i < 2; i++) {
                    ldsm4(fa[nxt][i],  sAh + aoff + ko16 + i * 16 * 144);
                    ldsm4(fal[nxt][i], sAl + aoff + ko16 + i * 16 * 144);
                }
#pragma unroll
                for (int jp = 0; jp < 2; jp++) {
                    ldsm4(fb[nxt][jp],  sBh + boff + ko16 + jp * 16 * 144);
                    ldsm4(fbl[nxt][jp], sBl + boff + ko16 + jp * 16 * 144);
                }
            }
#pragma unroll
            for (int i = 0; i < 2; i++)
#pragma unroll
                for (int j = 0; j < 4; j++) {
                    int jp = j >> 1, o = (j & 1) * 2;
                    mma16816(acc[i][j], fa[cur][i],  fb[cur][jp][o],  fb[cur][jp][o + 1]);
                    mma16816(acc[i][j], fa[cur][i],  fbl[cur][jp][o], fbl[cur][jp][o + 1]);
                    mma16816(acc[i][j], fal[cur][i], fb[cur][jp][o],  fb[cur][jp][o + 1]);
                }
        }
    }

    // epilogue: add mask, store masked logits
    const int* ms = (const int*)(smem + QK_MASKO);
#pragma unroll
    for (int j = 0; j < 4; j++) {
        int c0 = wn * 32 + j * 8 + 2 * tg;
        float t0 = (1.0f - (float)ms[c0]) * NEG_INF;
        float t1 = (1.0f - (float)ms[c0 + 1]) * NEG_INF;
#pragma unroll
        for (int i = 0; i < 2; i++) {
            int r0 = bm * 128 + wm * 32 + i * 16 + g;
            size_t base = ((size_t)bz * TQ + r0) * TK + bn * 128 + c0;
            *(float2*)(&S[base]) = make_float2(acc[i][j][0] + t0, acc[i][j][1] + t1);
            *(float2*)(&S[base + (size_t)8 * TK]) = make_float2(acc[i][j][2] + t0, acc[i][j][3] + t1);
        }
    }
}

// ------------------------------------------------------------ row softmax + split of P
__global__ __launch_bounds__(256) void softmax_split(float* __restrict__ W)
{
    const size_t row = blockIdx.x;
    float4* p = reinterpret_cast<float4*>(W + row * TK);
    const int tid = threadIdx.x;
    const int lane = tid & 31, warp = tid >> 5;
    __shared__ float red[8];

    float4 v0 = p[tid];
    float4 v1 = p[tid + 256];

    float mx = fmaxf(fmaxf(fmaxf(v0.x, v0.y), fmaxf(v0.z, v0.w)),
                     fmaxf(fmaxf(v1.x, v1.y), fmaxf(v1.z, v1.w)));
#pragma unroll
    for (int o = 16; o; o >>= 1) mx = fmaxf(mx, __shfl_xor_sync(0xffffffffu, mx, o));
    if (lane == 0) red[warp] = mx;
    __syncthreads();
    float bmax = red[0];
#pragma unroll
    for (int i = 1; i < 8; i++) bmax = fmaxf(bmax, red[i]);
    __syncthreads();

    v0.x = __expf(v0.x - bmax); v0.y = __expf(v0.y - bmax);
    v0.z = __expf(v0.z - bmax); v0.w = __expf(v0.w - bmax);
    v1.x = __expf(v1.x - bmax); v1.y = __expf(v1.y - bmax);
    v1.z = __expf(v1.z - bmax); v1.w = __expf(v1.w - bmax);

    float s = (v0.x + v0.y + v0.z + v0.w) + (v1.x + v1.y + v1.z + v1.w);
#pragma unroll
    for (int o = 16; o; o >>= 1) s += __shfl_xor_sync(0xffffffffu, s, o);
    if (lane == 0) red[warp] = s;
    __syncthreads();
    float bsum = red[0];
#pragma unroll
    for (int i = 1; i < 8; i++) bsum += red[i];

    const float inv = 1.0f / bsum;
    v0.x *= inv; v0.y *= inv; v0.z *= inv; v0.w *= inv;
    v1.x *= inv; v1.y *= inv; v1.z *= inv; v1.w *= inv;
    p[tid] = v0;
    p[tid + 256] = v1;

    // split P for the PV pass
    size_t i0 = row * (TK / 4) + tid;
    size_t i1 = i0 + 256;
    uint2 h, l;
    split4(v0, h, l);
    ((uint2*)g_p_h)[i0] = h;
    ((uint2*)g_p_l)[i0] = l;
    split4(v1, h, l);
    ((uint2*)g_p_h)[i1] = h;
    ((uint2*)g_p_l)[i1] = l;
}

// ------------------------------------------------------------ P @ V (fp16 2-term)
// tiles: Ph, Pl (K-major), Vh ([k][d], ldmatrix.trans). cp.async 3-stage ring.
__global__ __launch_bounds__(NT, 1) void pv_kernel(float* __restrict__ ctx)
{
    extern __shared__ char smem[];
    const int tid = threadIdx.x, warp = tid >> 5, lane = tid & 31;
    const int g = lane >> 2, tg = lane & 3;
    const int r8 = lane & 7, sub = lane >> 3;
    const int wm = warp >> 2, wn = warp & 3;
    const int bz = blockIdx.z, bm = blockIdx.y, bn = blockIdx.x;  // bn: d tile

    const __half* Ph_g = g_p_h + ((size_t)bz * TQ + bm * 128) * TK;
    const __half* Pl_g = g_p_l + ((size_t)bz * TQ + bm * 128) * TK;
    const __half* Vh_g = g_enc_h + (size_t)bz * TK * D + bn * 128;

    const uint32_t sb = smem_u32(smem);

    auto issue = [&](int k) {
        char* base = smem + (k % 3) * PV_STAGE;
        const int ko = k * KC;
#pragma unroll
        for (int t = 0; t < 2; t++) {
            char* dstT = base + t * PV_PTILE;
            const __half* src = (t == 0 ? Ph_g : Pl_g) + ko;
#pragma unroll
            for (int j = 0; j < 2; j++) {
                int u = tid + NT * j, r = u >> 3, c = u & 7;
                cp_async16(smem_u32(dstT + r * 144 + c * 16), src + (size_t)r * TK + c * 8);
            }
        }
        char* dstV = base + 2 * PV_PTILE;
#pragma unroll
        for (int j = 0; j < 2; j++) {
            int u = tid + NT * j, r = u >> 4, c = u & 15;
            cp_async16(smem_u32(dstV + r * 272 + c * 16), Vh_g + (size_t)(ko + r) * D + c * 8);
        }
    };

    issue(0); cp_commit();
    issue(1); cp_commit();

    float acc[2][4][4];
#pragma unroll
    for (int i = 0; i < 2; i++)
#pragma unroll
        for (int j = 0; j < 4; j++)
#pragma unroll
            for (int t = 0; t < 4; t++) acc[i][j][t] = 0.f;

    const uint32_t aoff = (wm * 32 + r8 + (sub & 1) * 8) * 144 + ((sub >> 1) * 8) * 2;
    const uint32_t voff = (r8 + (sub & 1) * 8) * 272 + (wn * 32 + (sub >> 1) * 8) * 2;

    for (int k = 0; k < PV_CHUNKS; k++) {
        cp_wait<1>();
        __syncthreads();
        if (k + 2 < PV_CHUNKS) issue(k + 2);
        cp_commit();

        const uint32_t sPh = sb + (k % 3) * PV_STAGE;
        const uint32_t sPl = sPh + PV_PTILE;
        const uint32_t sVh = sPl + PV_PTILE;

        uint32_t fa[2][2][4], fal[2][2][4], fv[2][2][4];
#pragma unroll
        for (int i = 0; i < 2; i++) {
            ldsm4(fa[0][i],  sPh + aoff + i * 16 * 144);
            ldsm4(fal[0][i], sPl + aoff + i * 16 * 144);
        }
#pragma unroll
        for (int jp = 0; jp < 2; jp++)
            ldsm4t(fv[0][jp], sVh + voff + jp * 16 * 2);

#pragma unroll
        for (int kk = 0; kk < 4; kk++) {
            const int cur = kk & 1, nxt = cur ^ 1;
            if (kk < 3) {
                const uint32_t ko16 = (kk + 1) * 32;
#pragma unroll
                for (int i = 0; i < 2; i++) {
                    ldsm4(fa[nxt][i],  sPh + aoff + ko16 + i * 16 * 144);
                    ldsm4(fal[nxt][i], sPl + aoff + ko16 + i * 16 * 144);
                }
#pragma unroll
                for (int jp = 0; jp < 2; jp++)
                    ldsm4t(fv[nxt][jp], sVh + voff + (kk + 1) * 16 * 272 + jp * 16 * 2);
            }
#pragma unroll
            for (int i = 0; i < 2; i++)
#pragma unroll
                for (int j = 0; j < 4; j++) {
                    int jp = j >> 1, o = (j & 1) * 2;
                    mma16816(acc[i][j], fa[cur][i],  fv[cur][jp][o], fv[cur][jp][o + 1]);
                    mma16816(acc[i][j], fal[cur][i], fv[cur][jp][o], fv[cur][jp][o + 1]);
                }
        }
    }

#pragma unroll
    for (int j = 0; j < 4; j++) {
        int c0 = wn * 32 + j * 8 + 2 * tg;
#pragma unroll
        for (int i = 0; i < 2; i++) {
            int r0 = bm * 128 + wm * 32 + i * 16 + g;
            size_t base = ((size_t)bz * TQ + r0) * D + bn * 128 + c0;
            *(float2*)(&ctx[base]) = make_float2(acc[i][j][0], acc[i][j][1]);
            *(float2*)(&ctx[base + (size_t)8 * D]) = make_float2(acc[i][j][2], acc[i][j][3]);
        }
    }
}

// ---------------------------------------------------------------- launcher
extern "C" void kernel_launch(void* const* d_in, const int* in_sizes, int n_in,
                              void* d_out, int out_size)
{
    const float* dec  = (const float*)d_in[0];   // [B, TQ, D]
    const float* enc  = (const float*)d_in[1];   // [B, TK, D]
    const int*   mask = (const int*)d_in[2];     // [B, TK]
    float* out = (float*)d_out;

    float* ctx = out;                              // [B, TQ, D]
    float* Wgt = out + (size_t)B * TQ * D;         // [B, TQ, TK]

    cudaFuncSetAttribute(qk_kernel, cudaFuncAttributeMaxDynamicSharedMemorySize, QK_SMEM);
    cudaFuncSetAttribute(pv_kernel, cudaFuncAttributeMaxDynamicSharedMemorySize, PV_SMEM);

    split_inputs<<<(B * TQ * D / 4) / 256, 256>>>(dec, enc);

    dim3 g1(TK / 128, TQ / 128, B);
    qk_kernel<<<g1, NT, QK_SMEM>>>(mask, Wgt);

    softmax_split<<<B * TQ, 256>>>(Wgt);

    dim3 g3(D / 128, TQ / 128, B);
    pv_kernel<<<g3, NT, PV_SMEM>>>(ctx);
}

// round 10
// speedup vs baseline: 1.1051x; 1.1051x over previous
#include <cuda_runtime.h>
#include <cuda_fp16.h>
#include <cstdint>

// Problem dims (fixed by the dataset)
constexpr int B  = 8;
constexpr int TQ = 2048;
constexpr int TK = 2048;
constexpr int D  = 1024;
constexpr float NEG_INF = -1e9f;

// QK: KC=32, 2-stage, 82KB/CTA -> 2 CTAs/SM. PV: KC=64, 2-stage, 108KB/CTA.
constexpr int QK_KC = 32;
constexpr int PV_KC = 64;
constexpr int QK_CHUNKS = D  / QK_KC;     // 32
constexpr int PV_CHUNKS = TK / PV_KC;     // 32

constexpr int QK_TILE  = 128 * 80;                // rows 128, pitch 80B (40 halfs)
constexpr int QK_STAGE = 4 * QK_TILE;             // Ah, Al, Bh, Bl = 40960
constexpr int QK_MASKO = 2 * QK_STAGE;            // 81920
constexpr int QK_SMEM  = QK_MASKO + 512;

constexpr int PV_PTILE = 128 * 144;               // rows 128, pitch 144B (72 halfs)
constexpr int PV_VTILE = 64 * 272;                // rows 64,  pitch 272B
constexpr int PV_STAGE = 2 * PV_PTILE + PV_VTILE; // 54272
constexpr int PV_SMEM  = 2 * PV_STAGE;            // 108544

constexpr int NT = 256;                   // 8 warps, 2x4 grid, warp tile 64x32

// ------------------------------------------------ device scratch (sanctioned)
__device__ __align__(16) __half g_dec_h[(size_t)B * TQ * D];
__device__ __align__(16) __half g_dec_l[(size_t)B * TQ * D];
__device__ __align__(16) __half g_enc_h[(size_t)B * TK * D];
__device__ __align__(16) __half g_enc_l[(size_t)B * TK * D];
__device__ __align__(16) __half g_p_h[(size_t)B * TQ * TK];
__device__ __align__(16) __half g_p_l[(size_t)B * TQ * TK];

// ---------------------------------------------------------------- helpers
__device__ __forceinline__ uint32_t smem_u32(const void* p) {
    return (uint32_t)__cvta_generic_to_shared(p);
}
__device__ __forceinline__ void cp_async16(uint32_t dst, const void* src) {
    asm volatile("cp.async.cg.shared.global [%0], [%1], 16;\n" :: "r"(dst), "l"(src));
}
__device__ __forceinline__ void cp_commit() {
    asm volatile("cp.async.commit_group;\n");
}
template <int N> __device__ __forceinline__ void cp_wait() {
    asm volatile("cp.async.wait_group %0;\n" :: "n"(N));
}
__device__ __forceinline__ void ldsm4(uint32_t r[4], uint32_t addr) {
    asm volatile("ldmatrix.sync.aligned.m8n8.x4.shared.b16 {%0,%1,%2,%3}, [%4];"
                 : "=r"(r[0]), "=r"(r[1]), "=r"(r[2]), "=r"(r[3]) : "r"(addr));
}
__device__ __forceinline__ void ldsm4t(uint32_t r[4], uint32_t addr) {
    asm volatile("ldmatrix.sync.aligned.m8n8.x4.trans.shared.b16 {%0,%1,%2,%3}, [%4];"
                 : "=r"(r[0]), "=r"(r[1]), "=r"(r[2]), "=r"(r[3]) : "r"(addr));
}
__device__ __forceinline__ void mma16816(float c[4], const uint32_t a[4],
                                         uint32_t b0, uint32_t b1) {
    asm volatile(
        "mma.sync.aligned.m16n8k16.row.col.f32.f16.f16.f32 "
        "{%0,%1,%2,%3},{%4,%5,%6,%7},{%8,%9},{%0,%1,%2,%3};\n"
        : "+f"(c[0]), "+f"(c[1]), "+f"(c[2]), "+f"(c[3])
        : "r"(a[0]), "r"(a[1]), "r"(a[2]), "r"(a[3]), "r"(b0), "r"(b1));
}
__device__ __forceinline__ void split4(float4 v, uint2& hi, uint2& lo) {
    __half2 h0 = __float22half2_rn(make_float2(v.x, v.y));
    __half2 h1 = __float22half2_rn(make_float2(v.z, v.w));
    float2 f0 = __half22float2(h0), f1 = __half22float2(h1);
    __half2 l0 = __float22half2_rn(make_float2(v.x - f0.x, v.y - f0.y));
    __half2 l1 = __float22half2_rn(make_float2(v.z - f1.x, v.w - f1.y));
    hi = make_uint2(*(uint32_t*)&h0, *(uint32_t*)&h1);
    lo = make_uint2(*(uint32_t*)&l0, *(uint32_t*)&l1);
}

// ------------------------------------------------------------ input pre-split
__global__ __launch_bounds__(256) void split_inputs(
    const float* __restrict__ dec, const float* __restrict__ enc)
{
    size_t i = (size_t)blockIdx.x * 256 + threadIdx.x;   // float4 index
    float4 v = ((const float4*)dec)[i];
    uint2 h, l;
    split4(v, h, l);
    ((uint2*)g_dec_h)[i] = h;
    ((uint2*)g_dec_l)[i] = l;
    v = ((const float4*)enc)[i];
    split4(v, h, l);
    ((uint2*)g_enc_h)[i] = h;
    ((uint2*)g_enc_l)[i] = l;
}

// ------------------------------------------------------------ QK^T + mask (fp16 3-term)
// Block tile 128x128x32, 8 warps 2x4 (warp tile 64x32), 2 CTAs/SM.
__global__ __launch_bounds__(NT, 2) void qk_kernel(
    const int* __restrict__ mask, float* __restrict__ S)
{
    extern __shared__ char smem[];
    const int tid = threadIdx.x, warp = tid >> 5, lane = tid & 31;
    const int g = lane >> 2, tg = lane & 3;
    const int r8 = lane & 7, sub = lane >> 3;
    const int wm = warp >> 2, wn = warp & 3;   // 2 x 4 warp grid
    const int bz = blockIdx.z, bm = blockIdx.y, bn = blockIdx.x;

    if (tid < 128) ((int*)(smem + QK_MASKO))[tid] = mask[bz * TK + bn * 128 + tid];

    const __half* srcs[4] = {
        g_dec_h + ((size_t)bz * TQ + bm * 128) * D,
        g_dec_l + ((size_t)bz * TQ + bm * 128) * D,
        g_enc_h + ((size_t)bz * TK + bn * 128) * D,
        g_enc_l + ((size_t)bz * TK + bn * 128) * D };

    const uint32_t sb = smem_u32(smem);

    // issue one chunk's 4 tiles into stage k&1 (each tile: 128 rows x 64B, pitch 80B)
    auto issue = [&](int k) {
        char* base = smem + (k & 1) * QK_STAGE;
        const int ko = k * QK_KC;
#pragma unroll
        for (int t = 0; t < 4; t++) {
            char* dstT = base + t * QK_TILE;
            const __half* src = srcs[t] + ko;
#pragma unroll
            for (int j = 0; j < 2; j++) {
                int u = tid + NT * j, r = u >> 2, c = u & 3;
                cp_async16(smem_u32(dstT + r * 80 + c * 16), src + (size_t)r * D + c * 8);
            }
        }
    };

    issue(0); cp_commit();

    float acc[4][4][4];
#pragma unroll
    for (int i = 0; i < 4; i++)
#pragma unroll
        for (int j = 0; j < 4; j++)
#pragma unroll
            for (int t = 0; t < 4; t++) acc[i][j][t] = 0.f;

    const uint32_t aoff = (wm * 64 + r8 + (sub & 1) * 8) * 80 + ((sub >> 1) * 8) * 2;
    const uint32_t boff = (wn * 32 + r8 + (sub >> 1) * 8) * 80 + ((sub & 1) * 8) * 2;

    for (int k = 0; k < QK_CHUNKS; k++) {
        cp_wait<0>();
        __syncthreads();               // chunk k landed; all done reading stage (k+1)&1
        if (k + 1 < QK_CHUNKS) { issue(k + 1); cp_commit(); }

        const uint32_t sAh = sb + (k & 1) * QK_STAGE;
        const uint32_t sAl = sAh + QK_TILE;
        const uint32_t sBh = sAl + QK_TILE;
        const uint32_t sBl = sBh + QK_TILE;

#pragma unroll
        for (int kk = 0; kk < 2; kk++) {
            const uint32_t ko16 = kk * 32;   // 16 halfs = 32 B
            uint32_t fah[4][4], fal[4][4], fbh[2][4], fbl[2][4];
#pragma unroll
            for (int i = 0; i < 4; i++) {
                ldsm4(fah[i], sAh + aoff + ko16 + i * 16 * 80);
                ldsm4(fal[i], sAl + aoff + ko16 + i * 16 * 80);
            }
#pragma unroll
            for (int jp = 0; jp < 2; jp++) {
                ldsm4(fbh[jp], sBh + boff + ko16 + jp * 16 * 80);
                ldsm4(fbl[jp], sBl + boff + ko16 + jp * 16 * 80);
            }
#pragma unroll
            for (int i = 0; i < 4; i++)
#pragma unroll
                for (int j = 0; j < 4; j++) {
                    int jp = j >> 1, o = (j & 1) * 2;
                    mma16816(acc[i][j], fah[i], fbh[jp][o], fbh[jp][o + 1]);
                    mma16816(acc[i][j], fah[i], fbl[jp][o], fbl[jp][o + 1]);
                    mma16816(acc[i][j], fal[i], fbh[jp][o], fbh[jp][o + 1]);
                }
        }
    }

    // epilogue: add mask, store masked logits
    const int* ms = (const int*)(smem + QK_MASKO);
#pragma unroll
    for (int j = 0; j < 4; j++) {
        int c0 = wn * 32 + j * 8 + 2 * tg;
        float t0 = (1.0f - (float)ms[c0]) * NEG_INF;
        float t1 = (1.0f - (float)ms[c0 + 1]) * NEG_INF;
#pragma unroll
        for (int i = 0; i < 4; i++) {
            int r0 = bm * 128 + wm * 64 + i * 16 + g;
            size_t base = ((size_t)bz * TQ + r0) * TK + bn * 128 + c0;
            *(float2*)(&S[base]) = make_float2(acc[i][j][0] + t0, acc[i][j][1] + t1);
            *(float2*)(&S[base + (size_t)8 * TK]) = make_float2(acc[i][j][2] + t0, acc[i][j][3] + t1);
        }
    }
}

// ------------------------------------------------------------ row softmax + split of P
__global__ __launch_bounds__(256) void softmax_split(float* __restrict__ W)
{
    const size_t row = blockIdx.x;
    float4* p = reinterpret_cast<float4*>(W + row * TK);
    const int tid = threadIdx.x;
    const int lane = tid & 31, warp = tid >> 5;
    __shared__ float red[8];

    float4 v0 = p[tid];
    float4 v1 = p[tid + 256];

    float mx = fmaxf(fmaxf(fmaxf(v0.x, v0.y), fmaxf(v0.z, v0.w)),
                     fmaxf(fmaxf(v1.x, v1.y), fmaxf(v1.z, v1.w)));
#pragma unroll
    for (int o = 16; o; o >>= 1) mx = fmaxf(mx, __shfl_xor_sync(0xffffffffu, mx, o));
    if (lane == 0) red[warp] = mx;
    __syncthreads();
    float bmax = red[0];
#pragma unroll
    for (int i = 1; i < 8; i++) bmax = fmaxf(bmax, red[i]);
    __syncthreads();

    v0.x = __expf(v0.x - bmax); v0.y = __expf(v0.y - bmax);
    v0.z = __expf(v0.z - bmax); v0.w = __expf(v0.w - bmax);
    v1.x = __expf(v1.x - bmax); v1.y = __expf(v1.y - bmax);
    v1.z = __expf(v1.z - bmax); v1.w = __expf(v1.w - bmax);

    float s = (v0.x + v0.y + v0.z + v0.w) + (v1.x + v1.y + v1.z + v1.w);
#pragma unroll
    for (int o = 16; o; o >>= 1) s += __shfl_xor_sync(0xffffffffu, s, o);
    if (lane == 0) red[warp] = s;
    __syncthreads();
    float bsum = red[0];
#pragma unroll
    for (int i = 1; i < 8; i++) bsum += red[i];

    const float inv = 1.0f / bsum;
    v0.x *= inv; v0.y *= inv; v0.z *= inv; v0.w *= inv;
    v1.x *= inv; v1.y *= inv; v1.z *= inv; v1.w *= inv;
    p[tid] = v0;
    p[tid + 256] = v1;

    // split P for the PV pass
    size_t i0 = row * (TK / 4) + tid;
    size_t i1 = i0 + 256;
    uint2 h, l;
    split4(v0, h, l);
    ((uint2*)g_p_h)[i0] = h;
    ((uint2*)g_p_l)[i0] = l;
    split4(v1, h, l);
    ((uint2*)g_p_h)[i1] = h;
    ((uint2*)g_p_l)[i1] = l;
}

// ------------------------------------------------------------ P @ V (fp16 2-term)
// Block tile 128x128x64, 8 warps 2x4 (warp tile 64x32), 2 CTAs/SM.
__global__ __launch_bounds__(NT, 2) void pv_kernel(float* __restrict__ ctx)
{
    extern __shared__ char smem[];
    const int tid = threadIdx.x, warp = tid >> 5, lane = tid & 31;
    const int g = lane >> 2, tg = lane & 3;
    const int r8 = lane & 7, sub = lane >> 3;
    const int wm = warp >> 2, wn = warp & 3;
    const int bz = blockIdx.z, bm = blockIdx.y, bn = blockIdx.x;  // bn: d tile

    const __half* Ph_g = g_p_h + ((size_t)bz * TQ + bm * 128) * TK;
    const __half* Pl_g = g_p_l + ((size_t)bz * TQ + bm * 128) * TK;
    const __half* Vh_g = g_enc_h + (size_t)bz * TK * D + bn * 128;

    const uint32_t sb = smem_u32(smem);

    auto issue = [&](int k) {
        char* base = smem + (k & 1) * PV_STAGE;
        const int ko = k * PV_KC;
#pragma unroll
        for (int t = 0; t < 2; t++) {
            char* dstT = base + t * PV_PTILE;
            const __half* src = (t == 0 ? Ph_g : Pl_g) + ko;
#pragma unroll
            for (int j = 0; j < 4; j++) {
                int u = tid + NT * j, r = u >> 3, c = u & 7;
                cp_async16(smem_u32(dstT + r * 144 + c * 16), src + (size_t)r * TK + c * 8);
            }
        }
        char* dstV = base + 2 * PV_PTILE;
#pragma unroll
        for (int j = 0; j < 4; j++) {
            int u = tid + NT * j, r = u >> 4, c = u & 15;
            cp_async16(smem_u32(dstV + r * 272 + c * 16), Vh_g + (size_t)(ko + r) * D + c * 8);
        }
    };

    issue(0); cp_commit();

    float acc[4][4][4];
#pragma unroll
    for (int i = 0; i < 4; i++)
#pragma unroll
        for (int j = 0; j < 4; j++)
#pragma unroll
            for (int t = 0; t < 4; t++) acc[i][j][t] = 0.f;

    const uint32_t aoff = (wm * 64 + r8 + (sub & 1) * 8) * 144 + ((sub >> 1) * 8) * 2;
    const uint32_t voff = (r8 + (sub & 1) * 8) * 272 + (wn * 32 + (sub >> 1) * 8) * 2;

    for (int k = 0; k < PV_CHUNKS; k++) {
        cp_wait<0>();
        __syncthreads();
        if (k + 1 < PV_CHUNKS) { issue(k + 1); cp_commit(); }

        const uint32_t sPh = sb + (k & 1) * PV_STAGE;
        const uint32_t sPl = sPh + PV_PTILE;
        const uint32_t sVh = sPl + PV_PTILE;

#pragma unroll
        for (int kk = 0; kk < 4; kk++) {
            uint32_t fa[4][4], fal[4][4], fv[2][4];
#pragma unroll
            for (int i = 0; i < 4; i++) {
                ldsm4(fa[i],  sPh + aoff + kk * 32 + i * 16 * 144);
                ldsm4(fal[i], sPl + aoff + kk * 32 + i * 16 * 144);
            }
#pragma unroll
            for (int jp = 0; jp < 2; jp++)
                ldsm4t(fv[jp], sVh + voff + kk * 16 * 272 + jp * 16 * 2);
#pragma unroll
            for (int i = 0; i < 4; i++)
#pragma unroll
                for (int j = 0; j < 4; j++) {
                    int jp = j >> 1, o = (j & 1) * 2;
                    mma16816(acc[i][j], fa[i],  fv[jp][o], fv[jp][o + 1]);
                    mma16816(acc[i][j], fal[i], fv[jp][o], fv[jp][o + 1]);
                }
        }
    }

#pragma unroll
    for (int j = 0; j < 4; j++) {
        int c0 = wn * 32 + j * 8 + 2 * tg;
#pragma unroll
        for (int i = 0; i < 4; i++) {
            int r0 = bm * 128 + wm * 64 + i * 16 + g;
            size_t base = ((size_t)bz * TQ + r0) * D + bn * 128 + c0;
            *(float2*)(&ctx[base]) = make_float2(acc[i][j][0], acc[i][j][1]);
            *(float2*)(&ctx[base + (size_t)8 * D]) = make_float2(acc[i][j][2], acc[i][j][3]);
        }
    }
}

// ---------------------------------------------------------------- launcher
extern "C" void kernel_launch(void* const* d_in, const int* in_sizes, int n_in,
                              void* d_out, int out_size)
{
    const float* dec  = (const float*)d_in[0];   // [B, TQ, D]
    const float* enc  = (const float*)d_in[1];   // [B, TK, D]
    const int*   mask = (const int*)d_in[2];     // [B, TK]
    float* out = (float*)d_out;

    float* ctx = out;                              // [B, TQ, D]
    float* Wgt = out + (size_t)B * TQ * D;         // [B, TQ, TK]

    cudaFuncSetAttribute(qk_kernel, cudaFuncAttributeMaxDynamicSharedMemorySize, QK_SMEM);
    cudaFuncSetAttribute(pv_kernel, cudaFuncAttributeMaxDynamicSharedMemorySize, PV_SMEM);

    split_inputs<<<(B * TQ * D / 4) / 256, 256>>>(dec, enc);

    dim3 g1(TK / 128, TQ / 128, B);
    qk_kernel<<<g1, NT, QK_SMEM>>>(mask, Wgt);

    softmax_split<<<B * TQ, 256>>>(Wgt);

    dim3 g3(D / 128, TQ / 128, B);
    pv_kernel<<<g3, NT, PV_SMEM>>>(ctx);
}

// round 11
// speedup vs baseline: 1.3116x; 1.1869x over previous
#include <cuda_runtime.h>
#include <cuda_fp16.h>
#include <cstdint>

// Problem dims (fixed by the dataset)
constexpr int B  = 8;
constexpr int TQ = 2048;
constexpr int TK = 2048;
constexpr int D  = 1024;
constexpr float NEG_INF = -1e9f;

// QK: KC=32, 2-stage, 82KB/CTA -> 2 CTAs/SM. PV: KC=64, 2-stage, 70KB/CTA.
constexpr int QK_KC = 32;
constexpr int PV_KC = 64;
constexpr int QK_CHUNKS = D  / QK_KC;     // 32
constexpr int PV_CHUNKS = TK / PV_KC;     // 32

constexpr int QK_TILE  = 128 * 80;                // rows 128, pitch 80B (40 halfs)
constexpr int QK_STAGE = 4 * QK_TILE;             // Ah, Al, Bh, Bl = 40960
constexpr int QK_MASKO = 2 * QK_STAGE;            // 81920
constexpr int QK_SMEM  = QK_MASKO + 512;

constexpr int PV_PTILE = 128 * 144;               // rows 128, pitch 144B (72 halfs)
constexpr int PV_VTILE = 64 * 272;                // rows 64,  pitch 272B
constexpr int PV_STAGE = PV_PTILE + PV_VTILE;     // 35840
constexpr int PV_SMEM  = 2 * PV_STAGE;            // 71680

constexpr int NT = 256;                   // 8 warps, 2x4 grid, warp tile 64x32

// ------------------------------------------------ device scratch (sanctioned)
__device__ __align__(16) __half g_dec_h[(size_t)B * TQ * D];
__device__ __align__(16) __half g_dec_l[(size_t)B * TQ * D];
__device__ __align__(16) __half g_enc_h[(size_t)B * TK * D];
__device__ __align__(16) __half g_enc_l[(size_t)B * TK * D];
__device__ __align__(16) __half g_p_h[(size_t)B * TQ * TK];

// ---------------------------------------------------------------- helpers
__device__ __forceinline__ uint32_t smem_u32(const void* p) {
    return (uint32_t)__cvta_generic_to_shared(p);
}
__device__ __forceinline__ void cp_async16(uint32_t dst, const void* src) {
    asm volatile("cp.async.cg.shared.global [%0], [%1], 16;\n" :: "r"(dst), "l"(src));
}
__device__ __forceinline__ void cp_commit() {
    asm volatile("cp.async.commit_group;\n");
}
template <int N> __device__ __forceinline__ void cp_wait() {
    asm volatile("cp.async.wait_group %0;\n" :: "n"(N));
}
__device__ __forceinline__ void ldsm4(uint32_t r[4], uint32_t addr) {
    asm volatile("ldmatrix.sync.aligned.m8n8.x4.shared.b16 {%0,%1,%2,%3}, [%4];"
                 : "=r"(r[0]), "=r"(r[1]), "=r"(r[2]), "=r"(r[3]) : "r"(addr));
}
__device__ __forceinline__ void ldsm4t(uint32_t r[4], uint32_t addr) {
    asm volatile("ldmatrix.sync.aligned.m8n8.x4.trans.shared.b16 {%0,%1,%2,%3}, [%4];"
                 : "=r"(r[0]), "=r"(r[1]), "=r"(r[2]), "=r"(r[3]) : "r"(addr));
}
__device__ __forceinline__ void mma16816(float c[4], const uint32_t a[4],
                                         uint32_t b0, uint32_t b1) {
    asm volatile(
        "mma.sync.aligned.m16n8k16.row.col.f32.f16.f16.f32 "
        "{%0,%1,%2,%3},{%4,%5,%6,%7},{%8,%9},{%0,%1,%2,%3};\n"
        : "+f"(c[0]), "+f"(c[1]), "+f"(c[2]), "+f"(c[3])
        : "r"(a[0]), "r"(a[1]), "r"(a[2]), "r"(a[3]), "r"(b0), "r"(b1));
}
__device__ __forceinline__ void split4(float4 v, uint2& hi, uint2& lo) {
    __half2 h0 = __float22half2_rn(make_float2(v.x, v.y));
    __half2 h1 = __float22half2_rn(make_float2(v.z, v.w));
    float2 f0 = __half22float2(h0), f1 = __half22float2(h1);
    __half2 l0 = __float22half2_rn(make_float2(v.x - f0.x, v.y - f0.y));
    __half2 l1 = __float22half2_rn(make_float2(v.z - f1.x, v.w - f1.y));
    hi = make_uint2(*(uint32_t*)&h0, *(uint32_t*)&h1);
    lo = make_uint2(*(uint32_t*)&l0, *(uint32_t*)&l1);
}
__device__ __forceinline__ uint2 rnd4(float4 v) {
    __half2 h0 = __float22half2_rn(make_float2(v.x, v.y));
    __half2 h1 = __float22half2_rn(make_float2(v.z, v.w));
    return make_uint2(*(uint32_t*)&h0, *(uint32_t*)&h1);
}

// ------------------------------------------------------------ input pre-split
__global__ __launch_bounds__(256) void split_inputs(
    const float* __restrict__ dec, const float* __restrict__ enc)
{
    size_t i = (size_t)blockIdx.x * 256 + threadIdx.x;   // float4 index
    float4 v = ((const float4*)dec)[i];
    uint2 h, l;
    split4(v, h, l);
    ((uint2*)g_dec_h)[i] = h;
    ((uint2*)g_dec_l)[i] = l;
    v = ((const float4*)enc)[i];
    split4(v, h, l);
    ((uint2*)g_enc_h)[i] = h;
    ((uint2*)g_enc_l)[i] = l;
}

// ------------------------------------------------------------ QK^T + mask (fp16 3-term)
// Block tile 128x128x32, 8 warps 2x4 (warp tile 64x32), 2 CTAs/SM.
__global__ __launch_bounds__(NT, 2) void qk_kernel(
    const int* __restrict__ mask, float* __restrict__ S)
{
    extern __shared__ char smem[];
    const int tid = threadIdx.x, warp = tid >> 5, lane = tid & 31;
    const int g = lane >> 2, tg = lane & 3;
    const int r8 = lane & 7, sub = lane >> 3;
    const int wm = warp >> 2, wn = warp & 3;   // 2 x 4 warp grid
    const int bz = blockIdx.z, bm = blockIdx.y, bn = blockIdx.x;

    if (tid < 128) ((int*)(smem + QK_MASKO))[tid] = mask[bz * TK + bn * 128 + tid];

    const __half* srcs[4] = {
        g_dec_h + ((size_t)bz * TQ + bm * 128) * D,
        g_dec_l + ((size_t)bz * TQ + bm * 128) * D,
        g_enc_h + ((size_t)bz * TK + bn * 128) * D,
        g_enc_l + ((size_t)bz * TK + bn * 128) * D };

    const uint32_t sb = smem_u32(smem);

    // issue one chunk's 4 tiles into stage k&1 (each tile: 128 rows x 64B, pitch 80B)
    auto issue = [&](int k) {
        char* base = smem + (k & 1) * QK_STAGE;
        const int ko = k * QK_KC;
#pragma unroll
        for (int t = 0; t < 4; t++) {
            char* dstT = base + t * QK_TILE;
            const __half* src = srcs[t] + ko;
#pragma unroll
            for (int j = 0; j < 2; j++) {
                int u = tid + NT * j, r = u >> 2, c = u & 3;
                cp_async16(smem_u32(dstT + r * 80 + c * 16), src + (size_t)r * D + c * 8);
            }
        }
    };

    issue(0); cp_commit();

    float acc[4][4][4];
#pragma unroll
    for (int i = 0; i < 4; i++)
#pragma unroll
        for (int j = 0; j < 4; j++)
#pragma unroll
            for (int t = 0; t < 4; t++) acc[i][j][t] = 0.f;

    const uint32_t aoff = (wm * 64 + r8 + (sub & 1) * 8) * 80 + ((sub >> 1) * 8) * 2;
    const uint32_t boff = (wn * 32 + r8 + (sub >> 1) * 8) * 80 + ((sub & 1) * 8) * 2;

    for (int k = 0; k < QK_CHUNKS; k++) {
        cp_wait<0>();
        __syncthreads();               // chunk k landed; all done reading stage (k+1)&1
        if (k + 1 < QK_CHUNKS) { issue(k + 1); cp_commit(); }

        const uint32_t sAh = sb + (k & 1) * QK_STAGE;
        const uint32_t sAl = sAh + QK_TILE;
        const uint32_t sBh = sAl + QK_TILE;
        const uint32_t sBl = sBh + QK_TILE;

#pragma unroll
        for (int kk = 0; kk < 2; kk++) {
            const uint32_t ko16 = kk * 32;   // 16 halfs = 32 B
            uint32_t fah[4][4], fal[4][4], fbh[2][4], fbl[2][4];
#pragma unroll
            for (int i = 0; i < 4; i++) {
                ldsm4(fah[i], sAh + aoff + ko16 + i * 16 * 80);
                ldsm4(fal[i], sAl + aoff + ko16 + i * 16 * 80);
            }
#pragma unroll
            for (int jp = 0; jp < 2; jp++) {
                ldsm4(fbh[jp], sBh + boff + ko16 + jp * 16 * 80);
                ldsm4(fbl[jp], sBl + boff + ko16 + jp * 16 * 80);
            }
#pragma unroll
            for (int i = 0; i < 4; i++)
#pragma unroll
                for (int j = 0; j < 4; j++) {
                    int jp = j >> 1, o = (j & 1) * 2;
                    mma16816(acc[i][j], fah[i], fbh[jp][o], fbh[jp][o + 1]);
                    mma16816(acc[i][j], fah[i], fbl[jp][o], fbl[jp][o + 1]);
                    mma16816(acc[i][j], fal[i], fbh[jp][o], fbh[jp][o + 1]);
                }
        }
    }

    // epilogue: add mask, store masked logits
    const int* ms = (const int*)(smem + QK_MASKO);
#pragma unroll
    for (int j = 0; j < 4; j++) {
        int c0 = wn * 32 + j * 8 + 2 * tg;
        float t0 = (1.0f - (float)ms[c0]) * NEG_INF;
        float t1 = (1.0f - (float)ms[c0 + 1]) * NEG_INF;
#pragma unroll
        for (int i = 0; i < 4; i++) {
            int r0 = bm * 128 + wm * 64 + i * 16 + g;
            size_t base = ((size_t)bz * TQ + r0) * TK + bn * 128 + c0;
            *(float2*)(&S[base]) = make_float2(acc[i][j][0] + t0, acc[i][j][1] + t1);
            *(float2*)(&S[base + (size_t)8 * TK]) = make_float2(acc[i][j][2] + t0, acc[i][j][3] + t1);
        }
    }
}

// ------------------------------------------------------------ row softmax + fp16 P
__global__ __launch_bounds__(256) void softmax_split(float* __restrict__ W)
{
    const size_t row = blockIdx.x;
    float4* p = reinterpret_cast<float4*>(W + row * TK);
    const int tid = threadIdx.x;
    const int lane = tid & 31, warp = tid >> 5;
    __shared__ float red[8];

    float4 v0 = p[tid];
    float4 v1 = p[tid + 256];

    float mx = fmaxf(fmaxf(fmaxf(v0.x, v0.y), fmaxf(v0.z, v0.w)),
                     fmaxf(fmaxf(v1.x, v1.y), fmaxf(v1.z, v1.w)));
#pragma unroll
    for (int o = 16; o; o >>= 1) mx = fmaxf(mx, __shfl_xor_sync(0xffffffffu, mx, o));
    if (lane == 0) red[warp] = mx;
    __syncthreads();
    float bmax = red[0];
#pragma unroll
    for (int i = 1; i < 8; i++) bmax = fmaxf(bmax, red[i]);
    __syncthreads();

    v0.x = __expf(v0.x - bmax); v0.y = __expf(v0.y - bmax);
    v0.z = __expf(v0.z - bmax); v0.w = __expf(v0.w - bmax);
    v1.x = __expf(v1.x - bmax); v1.y = __expf(v1.y - bmax);
    v1.z = __expf(v1.z - bmax); v1.w = __expf(v1.w - bmax);

    float s = (v0.x + v0.y + v0.z + v0.w) + (v1.x + v1.y + v1.z + v1.w);
#pragma unroll
    for (int o = 16; o; o >>= 1) s += __shfl_xor_sync(0xffffffffu, s, o);
    if (lane == 0) red[warp] = s;
    __syncthreads();
    float bsum = red[0];
#pragma unroll
    for (int i = 1; i < 8; i++) bsum += red[i];

    const float inv = 1.0f / bsum;
    v0.x *= inv; v0.y *= inv; v0.z *= inv; v0.w *= inv;
    v1.x *= inv; v1.y *= inv; v1.z *= inv; v1.w *= inv;
    p[tid] = v0;
    p[tid + 256] = v1;

    // fp16 P for the PV pass
    size_t i0 = row * (TK / 4) + tid;
    size_t i1 = i0 + 256;
    ((uint2*)g_p_h)[i0] = rnd4(v0);
    ((uint2*)g_p_h)[i1] = rnd4(v1);
}

// ------------------------------------------------------------ P @ V (fp16 1-term)
// Block tile 128x128x64, 8 warps 2x4 (warp tile 64x32), 2 CTAs/SM.
__global__ __launch_bounds__(NT, 2) void pv_kernel(float* __restrict__ ctx)
{
    extern __shared__ char smem[];
    const int tid = threadIdx.x, warp = tid >> 5, lane = tid & 31;
    const int g = lane >> 2, tg = lane & 3;
    const int r8 = lane & 7, sub = lane >> 3;
    const int wm = warp >> 2, wn = warp & 3;
    const int bz = blockIdx.z, bm = blockIdx.y, bn = blockIdx.x;  // bn: d tile

    const __half* Ph_g = g_p_h + ((size_t)bz * TQ + bm * 128) * TK;
    const __half* Vh_g = g_enc_h + (size_t)bz * TK * D + bn * 128;

    const uint32_t sb = smem_u32(smem);

    auto issue = [&](int k) {
        char* base = smem + (k & 1) * PV_STAGE;
        const int ko = k * PV_KC;
#pragma unroll
        for (int j = 0; j < 4; j++) {
            int u = tid + NT * j, r = u >> 3, c = u & 7;
            cp_async16(smem_u32(base + r * 144 + c * 16), Ph_g + ko + (size_t)r * TK + c * 8);
        }
        char* dstV = base + PV_PTILE;
#pragma unroll
        for (int j = 0; j < 4; j++) {
            int u = tid + NT * j, r = u >> 4, c = u & 15;
            cp_async16(smem_u32(dstV + r * 272 + c * 16), Vh_g + (size_t)(ko + r) * D + c * 8);
        }
    };

    issue(0); cp_commit();

    float acc[4][4][4];
#pragma unroll
    for (int i = 0; i < 4; i++)
#pragma unroll
        for (int j = 0; j < 4; j++)
#pragma unroll
            for (int t = 0; t < 4; t++) acc[i][j][t] = 0.f;

    const uint32_t aoff = (wm * 64 + r8 + (sub & 1) * 8) * 144 + ((sub >> 1) * 8) * 2;
    const uint32_t voff = (r8 + (sub & 1) * 8) * 272 + (wn * 32 + (sub >> 1) * 8) * 2;

    for (int k = 0; k < PV_CHUNKS; k++) {
        cp_wait<0>();
        __syncthreads();
        if (k + 1 < PV_CHUNKS) { issue(k + 1); cp_commit(); }

        const uint32_t sPh = sb + (k & 1) * PV_STAGE;
        const uint32_t sVh = sPh + PV_PTILE;

#pragma unroll
        for (int kk = 0; kk < 4; kk++) {
            uint32_t fa[4][4], fv[2][4];
#pragma unroll
            for (int i = 0; i < 4; i++)
                ldsm4(fa[i], sPh + aoff + kk * 32 + i * 16 * 144);
#pragma unroll
            for (int jp = 0; jp < 2; jp++)
                ldsm4t(fv[jp], sVh + voff + kk * 16 * 272 + jp * 16 * 2);
#pragma unroll
            for (int i = 0; i < 4; i++)
#pragma unroll
                for (int j = 0; j < 4; j++) {
                    int jp = j >> 1, o = (j & 1) * 2;
                    mma16816(acc[i][j], fa[i], fv[jp][o], fv[jp][o + 1]);
                }
        }
    }

#pragma unroll
    for (int j = 0; j < 4; j++) {
        int c0 = wn * 32 + j * 8 + 2 * tg;
#pragma unroll
        for (int i = 0; i < 4; i++) {
            int r0 = bm * 128 + wm * 64 + i * 16 + g;
            size_t base = ((size_t)bz * TQ + r0) * D + bn * 128 + c0;
            *(float2*)(&ctx[base]) = make_float2(acc[i][j][0], acc[i][j][1]);
            *(float2*)(&ctx[base + (size_t)8 * D]) = make_float2(acc[i][j][2], acc[i][j][3]);
        }
    }
}

// ---------------------------------------------------------------- launcher
extern "C" void kernel_launch(void* const* d_in, const int* in_sizes, int n_in,
                              void* d_out, int out_size)
{
    const float* dec  = (const float*)d_in[0];   // [B, TQ, D]
    const float* enc  = (const float*)d_in[1];   // [B, TK, D]
    const int*   mask = (const int*)d_in[2];     // [B, TK]
    float* out = (float*)d_out;

    float* ctx = out;                              // [B, TQ, D]
    float* Wgt = out + (size_t)B * TQ * D;         // [B, TQ, TK]

    cudaFuncSetAttribute(qk_kernel, cudaFuncAttributeMaxDynamicSharedMemorySize, QK_SMEM);
    cudaFuncSetAttribute(pv_kernel, cudaFuncAttributeMaxDynamicSharedMemorySize, PV_SMEM);

    split_inputs<<<(B * TQ * D / 4) / 256, 256>>>(dec, enc);

    dim3 g1(TK / 128, TQ / 128, B);
    qk_kernel<<<g1, NT, QK_SMEM>>>(mask, Wgt);

    softmax_split<<<B * TQ, 256>>>(Wgt);

    dim3 g3(D / 128, TQ / 128, B);
    pv_kernel<<<g3, NT, PV_SMEM>>>(ctx);
}